// round 1
// baseline (speedup 1.0000x reference)
#include <cuda_runtime.h>

#define LDIM 128
#define NMAX 50000
#define EMAX 800000

// Scratch (allocation-free rule: __device__ globals)
__device__ float g_xws[(size_t)NMAX * LDIM];  // (x@W) * dinv[row]
__device__ float g_A[(size_t)NMAX * LDIM];    // edge accumulator
__device__ int   g_deg[NMAX];                 // degree incl. self-loop

// ---------------------------------------------------------------------------
// K1: zero accumulator, deg = 1 (self loop)
// ---------------------------------------------------------------------------
__global__ void init_kernel(int N) {
    int i = blockIdx.x * blockDim.x + threadIdx.x;
    int total = N * LDIM;
    if (i < total) g_A[i] = 0.0f;
    if (i < N) g_deg[i] = 1;
}

// ---------------------------------------------------------------------------
// K2: degree count on destination nodes
// ---------------------------------------------------------------------------
__global__ void deg_kernel(const int* __restrict__ dst, int E) {
    int e = blockIdx.x * blockDim.x + threadIdx.x;
    if (e < E) atomicAdd(&g_deg[dst[e]], 1);
}

// ---------------------------------------------------------------------------
// K3: xws[row] = (x[row] @ W) * rsqrt(deg[row])
// 64 rows x 128 cols per block, 256 threads, each thread 4 rows x 8 cols.
// W (64KB) + x tile (32KB) in dynamic smem (96KB).
// ---------------------------------------------------------------------------
__global__ __launch_bounds__(256) void gemm_scale_kernel(
    const float* __restrict__ x, const float* __restrict__ W, int N)
{
    extern __shared__ float smem[];
    float* Ws = smem;                  // [128][128]
    float* xs = smem + LDIM * LDIM;    // [64][128]

    const int t = threadIdx.x;
    const int block_row = blockIdx.x * 64;

    // load W (full 128x128)
    #pragma unroll
    for (int i = t; i < LDIM * LDIM / 4; i += 256)
        ((float4*)Ws)[i] = ((const float4*)W)[i];

    // load x tile (64 rows), zero-pad out-of-range rows
    for (int i = t; i < 64 * LDIM / 4; i += 256) {
        int r = i >> 5;           // 32 float4 per row
        int c4 = i & 31;
        int row = block_row + r;
        float4 v = make_float4(0.f, 0.f, 0.f, 0.f);
        if (row < N) v = ((const float4*)x)[(size_t)row * (LDIM / 4) + c4];
        ((float4*)xs)[i] = v;
    }
    __syncthreads();

    const int tx = t & 15;        // 16 col-groups of 8
    const int ty = t >> 4;        // 16 row-groups of 4
    const int r0 = ty * 4;
    const int c0 = tx * 8;

    float acc[4][8];
    #pragma unroll
    for (int i = 0; i < 4; i++)
        #pragma unroll
        for (int j = 0; j < 8; j++) acc[i][j] = 0.0f;

    #pragma unroll 4
    for (int k4 = 0; k4 < LDIM / 4; k4++) {
        float4 a4[4];
        #pragma unroll
        for (int i = 0; i < 4; i++)
            a4[i] = *(const float4*)&xs[(r0 + i) * LDIM + k4 * 4];

        #pragma unroll
        for (int kk = 0; kk < 4; kk++) {
            int k = k4 * 4 + kk;
            float4 b0 = *(const float4*)&Ws[k * LDIM + c0];
            float4 b1 = *(const float4*)&Ws[k * LDIM + c0 + 4];
            float bv[8] = {b0.x, b0.y, b0.z, b0.w, b1.x, b1.y, b1.z, b1.w};
            #pragma unroll
            for (int i = 0; i < 4; i++) {
                float av = ((const float*)&a4[i])[kk];
                #pragma unroll
                for (int j = 0; j < 8; j++)
                    acc[i][j] = fmaf(av, bv[j], acc[i][j]);
            }
        }
    }

    // epilogue: scale by dinv[row], store
    #pragma unroll
    for (int i = 0; i < 4; i++) {
        int row = block_row + r0 + i;
        if (row < N) {
            float dinv = rsqrtf((float)g_deg[row]);
            float4 o0, o1;
            o0.x = acc[i][0] * dinv; o0.y = acc[i][1] * dinv;
            o0.z = acc[i][2] * dinv; o0.w = acc[i][3] * dinv;
            o1.x = acc[i][4] * dinv; o1.y = acc[i][5] * dinv;
            o1.z = acc[i][6] * dinv; o1.w = acc[i][7] * dinv;
            float* op = &g_xws[(size_t)row * LDIM + c0];
            *(float4*)op = o0;
            *(float4*)(op + 4) = o1;
        }
    }
}

// ---------------------------------------------------------------------------
// K4: one warp per edge: A[dst][:] += xws[src][:]
// ---------------------------------------------------------------------------
__global__ void scatter_kernel(const int* __restrict__ src,
                               const int* __restrict__ dst, int E)
{
    int gw = (blockIdx.x * blockDim.x + threadIdx.x) >> 5;
    int lane = threadIdx.x & 31;
    if (gw >= E) return;
    int s = __ldg(&src[gw]);
    int d = __ldg(&dst[gw]);
    float4 v = *(const float4*)&g_xws[(size_t)s * LDIM + lane * 4];
    float* p = &g_A[(size_t)d * LDIM + lane * 4];
    atomicAdd(p + 0, v.x);
    atomicAdd(p + 1, v.y);
    atomicAdd(p + 2, v.z);
    atomicAdd(p + 3, v.w);
}

// ---------------------------------------------------------------------------
// K5: out = softmax(relu(dinv*(A + xws) + b)), one warp per node
// ---------------------------------------------------------------------------
__global__ void finalize_kernel(const float* __restrict__ b,
                                float* __restrict__ out, int N)
{
    int gw = (blockIdx.x * blockDim.x + threadIdx.x) >> 5;
    int lane = threadIdx.x & 31;
    if (gw >= N) return;

    size_t base = (size_t)gw * LDIM + lane * 4;
    float4 a  = *(const float4*)&g_A[base];
    float4 w  = *(const float4*)&g_xws[base];
    float4 bb = *(const float4*)&b[lane * 4];
    float dinv = rsqrtf((float)g_deg[gw]);

    float v0 = fmaxf(fmaf(dinv, a.x + w.x, bb.x), 0.0f);
    float v1 = fmaxf(fmaf(dinv, a.y + w.y, bb.y), 0.0f);
    float v2 = fmaxf(fmaf(dinv, a.z + w.z, bb.z), 0.0f);
    float v3 = fmaxf(fmaf(dinv, a.w + w.w, bb.w), 0.0f);

    float m = fmaxf(fmaxf(v0, v1), fmaxf(v2, v3));
    #pragma unroll
    for (int off = 16; off > 0; off >>= 1)
        m = fmaxf(m, __shfl_xor_sync(0xFFFFFFFFu, m, off));

    float e0 = __expf(v0 - m);
    float e1 = __expf(v1 - m);
    float e2 = __expf(v2 - m);
    float e3 = __expf(v3 - m);
    float s = e0 + e1 + e2 + e3;
    #pragma unroll
    for (int off = 16; off > 0; off >>= 1)
        s += __shfl_xor_sync(0xFFFFFFFFu, s, off);

    float inv = __frcp_rn(s);
    float4 o;
    o.x = e0 * inv; o.y = e1 * inv; o.z = e2 * inv; o.w = e3 * inv;
    *(float4*)&out[base] = o;
}

// ---------------------------------------------------------------------------
extern "C" void kernel_launch(void* const* d_in, const int* in_sizes, int n_in,
                              void* d_out, int out_size)
{
    const float* x  = (const float*)d_in[0];
    const int*   ei = (const int*)d_in[1];
    const float* W  = (const float*)d_in[2];
    const float* b  = (const float*)d_in[3];
    float* out = (float*)d_out;

    int N = in_sizes[0] / LDIM;   // 50000
    int E = in_sizes[1] / 2;      // 800000
    const int* src = ei;
    const int* dst = ei + E;

    int initN = N * LDIM;
    init_kernel<<<(initN + 255) / 256, 256>>>(N);
    deg_kernel<<<(E + 255) / 256, 256>>>(dst, E);

    cudaFuncSetAttribute(gemm_scale_kernel,
                         cudaFuncAttributeMaxDynamicSharedMemorySize, 96 * 1024);
    gemm_scale_kernel<<<(N + 63) / 64, 256, 96 * 1024>>>(x, W, N);

    long long scatterThreads = (long long)E * 32;
    scatter_kernel<<<(int)((scatterThreads + 255) / 256), 256>>>(src, dst, E);

    long long finThreads = (long long)N * 32;
    finalize_kernel<<<(int)((finThreads + 255) / 256), 256>>>(b, out, N);
}

// round 2
// speedup vs baseline: 1.6995x; 1.6995x over previous
#include <cuda_runtime.h>

#define LDIM 128
#define NMAX 50000
#define EMAX 800000

// Scratch (allocation-free rule: __device__ globals). 16B alignment for v4 atomics.
__device__ __align__(16) float g_xws[(size_t)NMAX * LDIM];  // (x@W) * dinv[row]
__device__ __align__(16) float g_A[(size_t)NMAX * LDIM];    // edge accumulator
__device__ int g_deg[NMAX];                                 // degree incl. self-loop

// ---------------------------------------------------------------------------
// K1: zero accumulator, deg = 1 (self loop)
// ---------------------------------------------------------------------------
__global__ void init_kernel(int N) {
    int i = blockIdx.x * blockDim.x + threadIdx.x;
    int total = N * (LDIM / 4);
    if (i < total) ((float4*)g_A)[i] = make_float4(0.f, 0.f, 0.f, 0.f);
    if (i < N) g_deg[i] = 1;
}

// ---------------------------------------------------------------------------
// K2: degree count on destination nodes
// ---------------------------------------------------------------------------
__global__ void deg_kernel(const int* __restrict__ dst, int E) {
    int e = blockIdx.x * blockDim.x + threadIdx.x;
    if (e < E) atomicAdd(&g_deg[dst[e]], 1);
}

// ---------------------------------------------------------------------------
// K3: xws[row] = (x[row] @ W) * rsqrt(deg[row])
// 64 rows x 128 cols per block, 256 threads, each thread 4 rows x 8 cols.
// ---------------------------------------------------------------------------
__global__ __launch_bounds__(256) void gemm_scale_kernel(
    const float* __restrict__ x, const float* __restrict__ W, int N)
{
    extern __shared__ float smem[];
    float* Ws = smem;                  // [128][128]
    float* xs = smem + LDIM * LDIM;    // [64][128]

    const int t = threadIdx.x;
    const int block_row = blockIdx.x * 64;

    #pragma unroll
    for (int i = t; i < LDIM * LDIM / 4; i += 256)
        ((float4*)Ws)[i] = ((const float4*)W)[i];

    for (int i = t; i < 64 * LDIM / 4; i += 256) {
        int r = i >> 5;
        int c4 = i & 31;
        int row = block_row + r;
        float4 v = make_float4(0.f, 0.f, 0.f, 0.f);
        if (row < N) v = ((const float4*)x)[(size_t)row * (LDIM / 4) + c4];
        ((float4*)xs)[i] = v;
    }
    __syncthreads();

    const int tx = t & 15;
    const int ty = t >> 4;
    const int r0 = ty * 4;
    const int c0 = tx * 8;

    float acc[4][8];
    #pragma unroll
    for (int i = 0; i < 4; i++)
        #pragma unroll
        for (int j = 0; j < 8; j++) acc[i][j] = 0.0f;

    #pragma unroll 4
    for (int k4 = 0; k4 < LDIM / 4; k4++) {
        float4 a4[4];
        #pragma unroll
        for (int i = 0; i < 4; i++)
            a4[i] = *(const float4*)&xs[(r0 + i) * LDIM + k4 * 4];

        #pragma unroll
        for (int kk = 0; kk < 4; kk++) {
            int k = k4 * 4 + kk;
            float4 b0 = *(const float4*)&Ws[k * LDIM + c0];
            float4 b1 = *(const float4*)&Ws[k * LDIM + c0 + 4];
            float bv[8] = {b0.x, b0.y, b0.z, b0.w, b1.x, b1.y, b1.z, b1.w};
            #pragma unroll
            for (int i = 0; i < 4; i++) {
                float av = ((const float*)&a4[i])[kk];
                #pragma unroll
                for (int j = 0; j < 8; j++)
                    acc[i][j] = fmaf(av, bv[j], acc[i][j]);
            }
        }
    }

    #pragma unroll
    for (int i = 0; i < 4; i++) {
        int row = block_row + r0 + i;
        if (row < N) {
            float dinv = rsqrtf((float)g_deg[row]);
            float4 o0, o1;
            o0.x = acc[i][0] * dinv; o0.y = acc[i][1] * dinv;
            o0.z = acc[i][2] * dinv; o0.w = acc[i][3] * dinv;
            o1.x = acc[i][4] * dinv; o1.y = acc[i][5] * dinv;
            o1.z = acc[i][6] * dinv; o1.w = acc[i][7] * dinv;
            float* op = &g_xws[(size_t)row * LDIM + c0];
            *(float4*)op = o0;
            *(float4*)(op + 4) = o1;
        }
    }
}

// ---------------------------------------------------------------------------
// K4: one warp per edge: A[dst][:] += xws[src][:] using 128-bit vector red.
// ---------------------------------------------------------------------------
__global__ void scatter_kernel(const int* __restrict__ src,
                               const int* __restrict__ dst, int E)
{
    int gw = (blockIdx.x * blockDim.x + threadIdx.x) >> 5;
    int lane = threadIdx.x & 31;
    if (gw >= E) return;
    int s = __ldg(&src[gw]);
    int d = __ldg(&dst[gw]);
    float4 v = *(const float4*)&g_xws[(size_t)s * LDIM + lane * 4];
    float* p = &g_A[(size_t)d * LDIM + lane * 4];
    asm volatile("red.global.add.v4.f32 [%0], {%1, %2, %3, %4};"
                 :: "l"(p), "f"(v.x), "f"(v.y), "f"(v.z), "f"(v.w)
                 : "memory");
}

// ---------------------------------------------------------------------------
// K5: out = softmax(relu(dinv*(A + xws) + b)), one warp per node
// ---------------------------------------------------------------------------
__global__ void finalize_kernel(const float* __restrict__ b,
                                float* __restrict__ out, int N)
{
    int gw = (blockIdx.x * blockDim.x + threadIdx.x) >> 5;
    int lane = threadIdx.x & 31;
    if (gw >= N) return;

    size_t base = (size_t)gw * LDIM + lane * 4;
    float4 a  = *(const float4*)&g_A[base];
    float4 w  = *(const float4*)&g_xws[base];
    float4 bb = *(const float4*)&b[lane * 4];
    float dinv = rsqrtf((float)g_deg[gw]);

    float v0 = fmaxf(fmaf(dinv, a.x + w.x, bb.x), 0.0f);
    float v1 = fmaxf(fmaf(dinv, a.y + w.y, bb.y), 0.0f);
    float v2 = fmaxf(fmaf(dinv, a.z + w.z, bb.z), 0.0f);
    float v3 = fmaxf(fmaf(dinv, a.w + w.w, bb.w), 0.0f);

    float m = fmaxf(fmaxf(v0, v1), fmaxf(v2, v3));
    #pragma unroll
    for (int off = 16; off > 0; off >>= 1)
        m = fmaxf(m, __shfl_xor_sync(0xFFFFFFFFu, m, off));

    float e0 = __expf(v0 - m);
    float e1 = __expf(v1 - m);
    float e2 = __expf(v2 - m);
    float e3 = __expf(v3 - m);
    float s = e0 + e1 + e2 + e3;
    #pragma unroll
    for (int off = 16; off > 0; off >>= 1)
        s += __shfl_xor_sync(0xFFFFFFFFu, s, off);

    float inv = __frcp_rn(s);
    float4 o;
    o.x = e0 * inv; o.y = e1 * inv; o.z = e2 * inv; o.w = e3 * inv;
    *(float4*)&out[base] = o;
}

// ---------------------------------------------------------------------------
extern "C" void kernel_launch(void* const* d_in, const int* in_sizes, int n_in,
                              void* d_out, int out_size)
{
    const float* x  = (const float*)d_in[0];
    const int*   ei = (const int*)d_in[1];
    const float* W  = (const float*)d_in[2];
    const float* b  = (const float*)d_in[3];
    float* out = (float*)d_out;

    int N = in_sizes[0] / LDIM;   // 50000
    int E = in_sizes[1] / 2;      // 800000
    const int* src = ei;
    const int* dst = ei + E;

    int initN = N * (LDIM / 4);
    init_kernel<<<(initN + 255) / 256, 256>>>(N);
    deg_kernel<<<(E + 255) / 256, 256>>>(dst, E);

    cudaFuncSetAttribute(gemm_scale_kernel,
                         cudaFuncAttributeMaxDynamicSharedMemorySize, 96 * 1024);
    gemm_scale_kernel<<<(N + 63) / 64, 256, 96 * 1024>>>(x, W, N);

    long long scatterThreads = (long long)E * 32;
    scatter_kernel<<<(int)((scatterThreads + 255) / 256), 256>>>(src, dst, E);

    long long finThreads = (long long)N * 32;
    finalize_kernel<<<(int)((finThreads + 255) / 256), 256>>>(b, out, N);
}

// round 3
// speedup vs baseline: 2.3581x; 1.3875x over previous
#include <cuda_runtime.h>

#define LDIM 128
#define NMAX 50000
#define EMAX 800000
#define SCAN_BLK 1024
#define NCHUNK ((NMAX + SCAN_BLK - 1) / SCAN_BLK)

// Scratch (allocation-free rule: __device__ globals)
__device__ __align__(16) float g_xws[(size_t)NMAX * LDIM]; // (x@W)*dinv[row]
__device__ int g_cnt[NMAX];      // in-degree (excl. self loop)
__device__ int g_off[NMAX];      // CSR offsets (exclusive scan of cnt)
__device__ int g_cur[NMAX];      // fill cursors
__device__ int g_adj[EMAX];      // src indices bucketed by dst
__device__ int g_part[NCHUNK];   // scan partials

// ---------------------------------------------------------------------------
// K0: zero counters
// ---------------------------------------------------------------------------
__global__ void zero_kernel(int N) {
    int i = blockIdx.x * blockDim.x + threadIdx.x;
    if (i < N) { g_cnt[i] = 0; g_cur[i] = 0; }
}

// ---------------------------------------------------------------------------
// K1: histogram of dst
// ---------------------------------------------------------------------------
__global__ void hist_kernel(const int* __restrict__ dst, int E) {
    int e = blockIdx.x * blockDim.x + threadIdx.x;
    if (e < E) atomicAdd(&g_cnt[dst[e]], 1);
}

// ---------------------------------------------------------------------------
// K2a: per-chunk exclusive scan (1024 elems/block), emit chunk totals
// ---------------------------------------------------------------------------
__global__ __launch_bounds__(SCAN_BLK) void scan1_kernel(int N) {
    __shared__ int warpsum[32];
    int t = threadIdx.x, lane = t & 31, wid = t >> 5;
    int gid = blockIdx.x * SCAN_BLK + t;
    int v = (gid < N) ? g_cnt[gid] : 0;

    int x = v;
    #pragma unroll
    for (int off = 1; off < 32; off <<= 1) {
        int y = __shfl_up_sync(0xFFFFFFFFu, x, off);
        if (lane >= off) x += y;
    }
    if (lane == 31) warpsum[wid] = x;
    __syncthreads();
    if (wid == 0) {
        int w = warpsum[lane];
        #pragma unroll
        for (int off = 1; off < 32; off <<= 1) {
            int y = __shfl_up_sync(0xFFFFFFFFu, w, off);
            if (lane >= off) w += y;
        }
        warpsum[lane] = w;
    }
    __syncthreads();
    int warp_prefix = (wid == 0) ? 0 : warpsum[wid - 1];
    int excl = warp_prefix + x - v;
    if (gid < N) g_off[gid] = excl;
    if (t == SCAN_BLK - 1) g_part[blockIdx.x] = warp_prefix + x;
}

// K2b: serial scan of chunk totals (tiny)
__global__ void scan2_kernel(int nchunk) {
    if (threadIdx.x == 0) {
        int run = 0;
        for (int i = 0; i < nchunk; i++) { int t = g_part[i]; g_part[i] = run; run += t; }
    }
}

// K2c: add chunk offsets back
__global__ __launch_bounds__(SCAN_BLK) void scan3_kernel(int N) {
    int gid = blockIdx.x * SCAN_BLK + threadIdx.x;
    if (gid < N) g_off[gid] += g_part[blockIdx.x];
}

// ---------------------------------------------------------------------------
// K3: bucket fill: adj[off[d] + cur[d]++] = src
// ---------------------------------------------------------------------------
__global__ void fill_kernel(const int* __restrict__ src,
                            const int* __restrict__ dst, int E) {
    int e = blockIdx.x * blockDim.x + threadIdx.x;
    if (e >= E) return;
    int d = dst[e];
    int pos = g_off[d] + atomicAdd(&g_cur[d], 1);
    g_adj[pos] = src[e];
}

// ---------------------------------------------------------------------------
// K4: xws[row] = (x[row] @ W) * rsqrt(cnt[row]+1)
// ---------------------------------------------------------------------------
__global__ __launch_bounds__(256) void gemm_scale_kernel(
    const float* __restrict__ x, const float* __restrict__ W, int N)
{
    extern __shared__ float smem[];
    float* Ws = smem;
    float* xs = smem + LDIM * LDIM;

    const int t = threadIdx.x;
    const int block_row = blockIdx.x * 64;

    #pragma unroll
    for (int i = t; i < LDIM * LDIM / 4; i += 256)
        ((float4*)Ws)[i] = ((const float4*)W)[i];

    for (int i = t; i < 64 * LDIM / 4; i += 256) {
        int r = i >> 5;
        int c4 = i & 31;
        int row = block_row + r;
        float4 v = make_float4(0.f, 0.f, 0.f, 0.f);
        if (row < N) v = ((const float4*)x)[(size_t)row * (LDIM / 4) + c4];
        ((float4*)xs)[i] = v;
    }
    __syncthreads();

    const int tx = t & 15;
    const int ty = t >> 4;
    const int r0 = ty * 4;
    const int c0 = tx * 8;

    float acc[4][8];
    #pragma unroll
    for (int i = 0; i < 4; i++)
        #pragma unroll
        for (int j = 0; j < 8; j++) acc[i][j] = 0.0f;

    #pragma unroll 4
    for (int k4 = 0; k4 < LDIM / 4; k4++) {
        float4 a4[4];
        #pragma unroll
        for (int i = 0; i < 4; i++)
            a4[i] = *(const float4*)&xs[(r0 + i) * LDIM + k4 * 4];

        #pragma unroll
        for (int kk = 0; kk < 4; kk++) {
            int k = k4 * 4 + kk;
            float4 b0 = *(const float4*)&Ws[k * LDIM + c0];
            float4 b1 = *(const float4*)&Ws[k * LDIM + c0 + 4];
            float bv[8] = {b0.x, b0.y, b0.z, b0.w, b1.x, b1.y, b1.z, b1.w};
            #pragma unroll
            for (int i = 0; i < 4; i++) {
                float av = ((const float*)&a4[i])[kk];
                #pragma unroll
                for (int j = 0; j < 8; j++)
                    acc[i][j] = fmaf(av, bv[j], acc[i][j]);
            }
        }
    }

    #pragma unroll
    for (int i = 0; i < 4; i++) {
        int row = block_row + r0 + i;
        if (row < N) {
            float dinv = rsqrtf((float)(g_cnt[row] + 1));
            float4 o0, o1;
            o0.x = acc[i][0] * dinv; o0.y = acc[i][1] * dinv;
            o0.z = acc[i][2] * dinv; o0.w = acc[i][3] * dinv;
            o1.x = acc[i][4] * dinv; o1.y = acc[i][5] * dinv;
            o1.z = acc[i][6] * dinv; o1.w = acc[i][7] * dinv;
            float* op = &g_xws[(size_t)row * LDIM + c0];
            *(float4*)op = o0;
            *(float4*)(op + 4) = o1;
        }
    }
}

// ---------------------------------------------------------------------------
// K5: one warp per node: reg-accumulate neighbors, fuse finalize + softmax.
// ---------------------------------------------------------------------------
__global__ void gather_finalize_kernel(const float* __restrict__ b,
                                       float* __restrict__ out, int N)
{
    int gw = (blockIdx.x * blockDim.x + threadIdx.x) >> 5;
    int lane = threadIdx.x & 31;
    if (gw >= N) return;

    int start = g_off[gw];
    int len   = g_cnt[gw];
    const size_t lbase = (size_t)lane * 4;

    float4 acc = make_float4(0.f, 0.f, 0.f, 0.f);

    for (int base = 0; base < len; base += 32) {
        int idx = 0;
        if (base + lane < len) idx = __ldg(&g_adj[start + base + lane]);
        int m = min(32, len - base);
        int j = 0;
        // unrolled groups of 8 for MLP
        for (; j + 8 <= m; j += 8) {
            int s0 = __shfl_sync(0xFFFFFFFFu, idx, j + 0);
            int s1 = __shfl_sync(0xFFFFFFFFu, idx, j + 1);
            int s2 = __shfl_sync(0xFFFFFFFFu, idx, j + 2);
            int s3 = __shfl_sync(0xFFFFFFFFu, idx, j + 3);
            int s4 = __shfl_sync(0xFFFFFFFFu, idx, j + 4);
            int s5 = __shfl_sync(0xFFFFFFFFu, idx, j + 5);
            int s6 = __shfl_sync(0xFFFFFFFFu, idx, j + 6);
            int s7 = __shfl_sync(0xFFFFFFFFu, idx, j + 7);
            float4 v0 = *(const float4*)&g_xws[(size_t)s0 * LDIM + lbase];
            float4 v1 = *(const float4*)&g_xws[(size_t)s1 * LDIM + lbase];
            float4 v2 = *(const float4*)&g_xws[(size_t)s2 * LDIM + lbase];
            float4 v3 = *(const float4*)&g_xws[(size_t)s3 * LDIM + lbase];
            float4 v4 = *(const float4*)&g_xws[(size_t)s4 * LDIM + lbase];
            float4 v5 = *(const float4*)&g_xws[(size_t)s5 * LDIM + lbase];
            float4 v6 = *(const float4*)&g_xws[(size_t)s6 * LDIM + lbase];
            float4 v7 = *(const float4*)&g_xws[(size_t)s7 * LDIM + lbase];
            acc.x += v0.x + v1.x + v2.x + v3.x + v4.x + v5.x + v6.x + v7.x;
            acc.y += v0.y + v1.y + v2.y + v3.y + v4.y + v5.y + v6.y + v7.y;
            acc.z += v0.z + v1.z + v2.z + v3.z + v4.z + v5.z + v6.z + v7.z;
            acc.w += v0.w + v1.w + v2.w + v3.w + v4.w + v5.w + v6.w + v7.w;
        }
        for (; j < m; j++) {
            int s = __shfl_sync(0xFFFFFFFFu, idx, j);
            float4 v = *(const float4*)&g_xws[(size_t)s * LDIM + lbase];
            acc.x += v.x; acc.y += v.y; acc.z += v.z; acc.w += v.w;
        }
    }

    // self loop + normalize + bias + relu
    float4 w  = *(const float4*)&g_xws[(size_t)gw * LDIM + lbase];
    float4 bb = *(const float4*)&b[lbase];
    float dinv = rsqrtf((float)(len + 1));

    float v0 = fmaxf(fmaf(dinv, acc.x + w.x, bb.x), 0.0f);
    float v1 = fmaxf(fmaf(dinv, acc.y + w.y, bb.y), 0.0f);
    float v2 = fmaxf(fmaf(dinv, acc.z + w.z, bb.z), 0.0f);
    float v3 = fmaxf(fmaf(dinv, acc.w + w.w, bb.w), 0.0f);

    float m = fmaxf(fmaxf(v0, v1), fmaxf(v2, v3));
    #pragma unroll
    for (int off = 16; off > 0; off >>= 1)
        m = fmaxf(m, __shfl_xor_sync(0xFFFFFFFFu, m, off));

    float e0 = __expf(v0 - m);
    float e1 = __expf(v1 - m);
    float e2 = __expf(v2 - m);
    float e3 = __expf(v3 - m);
    float s = e0 + e1 + e2 + e3;
    #pragma unroll
    for (int off = 16; off > 0; off >>= 1)
        s += __shfl_xor_sync(0xFFFFFFFFu, s, off);

    float inv = __frcp_rn(s);
    float4 o;
    o.x = e0 * inv; o.y = e1 * inv; o.z = e2 * inv; o.w = e3 * inv;
    *(float4*)&out[(size_t)gw * LDIM + lbase] = o;
}

// ---------------------------------------------------------------------------
extern "C" void kernel_launch(void* const* d_in, const int* in_sizes, int n_in,
                              void* d_out, int out_size)
{
    const float* x  = (const float*)d_in[0];
    const int*   ei = (const int*)d_in[1];
    const float* W  = (const float*)d_in[2];
    const float* b  = (const float*)d_in[3];
    float* out = (float*)d_out;

    int N = in_sizes[0] / LDIM;   // 50000
    int E = in_sizes[1] / 2;      // 800000
    const int* src = ei;
    const int* dst = ei + E;
    int nchunk = (N + SCAN_BLK - 1) / SCAN_BLK;

    zero_kernel<<<(N + 255) / 256, 256>>>(N);
    hist_kernel<<<(E + 255) / 256, 256>>>(dst, E);
    scan1_kernel<<<nchunk, SCAN_BLK>>>(N);
    scan2_kernel<<<1, 32>>>(nchunk);
    scan3_kernel<<<nchunk, SCAN_BLK>>>(N);
    fill_kernel<<<(E + 255) / 256, 256>>>(src, dst, E);

    cudaFuncSetAttribute(gemm_scale_kernel,
                         cudaFuncAttributeMaxDynamicSharedMemorySize, 96 * 1024);
    gemm_scale_kernel<<<(N + 63) / 64, 256, 96 * 1024>>>(x, W, N);

    long long gthreads = (long long)N * 32;
    gather_finalize_kernel<<<(int)((gthreads + 255) / 256), 256>>>(b, out, N);
}